// round 1
// baseline (speedup 1.0000x reference)
#include <cuda_runtime.h>
#include <cuda_bf16.h>

// YOLOv1 loss: B=16384, S=7, 30 channels. N = B*S*S = 802816 cells.
// Kernel 1: per-block partial sums (float4: cls, conf, center+wh, noobj).
// Kernel 2: deterministic fp64 reduction + lambda scaling -> out[4].

#define NCELL (16384 * 7 * 7)   // 802816
#define BLK   128
#define NBLK  (NCELL / BLK)     // 6272 (exact)

__device__ float4 g_part[NBLK];

__global__ __launch_bounds__(BLK) void yolo_main(const float* __restrict__ P,
                                                 const float* __restrict__ T)
{
    __shared__ float SP[BLK * 30];
    __shared__ float ST[BLK * 30];
    const int tid = threadIdx.x;

    // ---- coalesced float4 staging of this block's 128 rows ----
    const size_t base = (size_t)blockIdx.x * (BLK * 30);
    const float4* gp = (const float4*)(P + base);
    const float4* gt = (const float4*)(T + base);
    float4* sp4 = (float4*)SP;
    float4* st4 = (float4*)ST;
    const int NV4 = BLK * 30 / 4;   // 960
    #pragma unroll
    for (int i = 0; i < (NV4 + BLK - 1) / BLK; ++i) {
        int idx = tid + i * BLK;
        if (idx < NV4) { sp4[idx] = gp[idx]; st4[idx] = gt[idx]; }
    }
    __syncthreads();

    const float* p = SP + tid * 30;
    const float* t = ST + tid * 30;
    const float CELL = 1.0f / 7.0f;

    const float t0 = t[0], t1 = t[1], t2 = t[2], t3 = t[3], tc = t[4];

    // target corners — faithful to the reference's in-place bug:
    //   xy1 = xy*CELL - wh*0.5 ;  xy2 = xy1*CELL + wh*0.5
    const float twx = t2 * t2, twy = t3 * t3;
    const float tx1 = t0 * CELL - 0.5f * twx;
    const float ty1 = t1 * CELL - 0.5f * twy;
    const float tx2 = tx1 * CELL + 0.5f * twx;
    const float ty2 = ty1 * CELL + 0.5f * twy;
    const float area_t = (tx2 - tx1) * (ty2 - ty1);

    float iou0, iou1;
    #pragma unroll
    for (int b = 0; b < 2; ++b) {
        const float px = p[b * 5 + 0], py = p[b * 5 + 1];
        const float pw = p[b * 5 + 2], ph = p[b * 5 + 3];
        const float pwx = pw * pw, pwy = ph * ph;
        const float x1 = px * CELL - 0.5f * pwx;
        const float y1 = py * CELL - 0.5f * pwy;
        const float x2 = x1 * CELL + 0.5f * pwx;
        const float y2 = y1 * CELL + 0.5f * pwy;
        const float ltx = fmaxf(x1, tx1), lty = fmaxf(y1, ty1);
        const float rbx = fminf(x2, tx2), rby = fminf(y2, ty2);
        const float dx = fmaxf(rbx - ltx, 0.0f);
        const float dy = fmaxf(rby - lty, 0.0f);
        const float inter  = dx * dy;
        const float area_p = (x2 - x1) * (y2 - y1);
        const float v = inter / (area_p + area_t - inter);
        if (b == 0) iou0 = v; else iou1 = v;
    }
    // jnp.argmax: first max wins on ties -> strict '>' for index 1
    const int bi = (iou1 > iou0) ? 1 : 0;
    const int b5 = bi * 5;

    // class column: first max over t[10:30]
    int kcol = 10;
    float vb = t[10];
    #pragma unroll
    for (int k = 11; k < 30; ++k) {
        float v = t[k];
        if (v > vb) { vb = v; kcol = k; }
    }

    const bool obj = (tc == 1.0f);
    const bool noo = (tc == 0.0f);

    const float dk = p[kcol]   - t[kcol];
    const float dc = p[b5 + 4] - t[b5 + 4];
    const float d0 = p[b5 + 0] - t[b5 + 0];
    const float d1 = p[b5 + 1] - t[b5 + 1];
    const float d2 = p[b5 + 2] - t[b5 + 2];
    const float d3 = p[b5 + 3] - t[b5 + 3];
    const float d4 = p[4] - tc;
    const float d9 = p[9] - t[9];

    float4 acc;
    acc.x = obj ? dk * dk : 0.0f;                                   // cls
    acc.y = obj ? dc * dc : 0.0f;                                   // conf
    acc.z = obj ? (d0 * d0 + d1 * d1 + d2 * d2 + d3 * d3) : 0.0f;   // center+wh
    acc.w = noo ? (d4 * d4 + d9 * d9) : 0.0f;                       // noobj

    // ---- block reduce: warp shuffles then smem ----
    #pragma unroll
    for (int o = 16; o > 0; o >>= 1) {
        acc.x += __shfl_down_sync(0xffffffffu, acc.x, o);
        acc.y += __shfl_down_sync(0xffffffffu, acc.y, o);
        acc.z += __shfl_down_sync(0xffffffffu, acc.z, o);
        acc.w += __shfl_down_sync(0xffffffffu, acc.w, o);
    }
    __shared__ float4 wsum[BLK / 32];
    if ((tid & 31) == 0) wsum[tid >> 5] = acc;
    __syncthreads();
    if (tid == 0) {
        float4 s = wsum[0];
        #pragma unroll
        for (int w = 1; w < BLK / 32; ++w) {
            s.x += wsum[w].x; s.y += wsum[w].y;
            s.z += wsum[w].z; s.w += wsum[w].w;
        }
        g_part[blockIdx.x] = s;
    }
}

__global__ __launch_bounds__(256) void yolo_reduce(float* __restrict__ out)
{
    __shared__ double s0[256], s1[256], s2[256], s3[256];
    const int tid = threadIdx.x;
    double a0 = 0.0, a1 = 0.0, a2 = 0.0, a3 = 0.0;
    for (int i = tid; i < NBLK; i += 256) {
        const float4 v = g_part[i];
        a0 += (double)v.x; a1 += (double)v.y;
        a2 += (double)v.z; a3 += (double)v.w;
    }
    s0[tid] = a0; s1[tid] = a1; s2[tid] = a2; s3[tid] = a3;
    __syncthreads();
    #pragma unroll
    for (int o = 128; o > 0; o >>= 1) {
        if (tid < o) {
            s0[tid] += s0[tid + o]; s1[tid] += s1[tid + o];
            s2[tid] += s2[tid + o]; s3[tid] += s3[tid + o];
        }
        __syncthreads();
    }
    if (tid == 0) {
        const float cls = (float)(5.0 * s0[0]);   // lambda_coord
        const float cnf = (float)(5.0 * s1[0]);
        const float cwh = (float)(5.0 * s2[0]);
        const float nob = (float)(0.5 * s3[0]);   // lambda_noobj
        out[0] = cls;
        out[1] = cnf;
        out[2] = cwh;
        out[3] = nob + cls + cnf + cwh;           // total
    }
}

extern "C" void kernel_launch(void* const* d_in, const int* in_sizes, int n_in,
                              void* d_out, int out_size)
{
    const float* P = (const float*)d_in[0];   // predictions [B,S,S,30] fp32
    const float* T = (const float*)d_in[1];   // targets     [B,S,S,30] fp32
    float* out = (float*)d_out;               // [cls, conf, center+wh, total]

    yolo_main<<<NBLK, BLK>>>(P, T);
    yolo_reduce<<<1, 256>>>(out);
}